// round 9
// baseline (speedup 1.0000x reference)
#include <cuda_runtime.h>
#include <cuda_bf16.h>
#include <math.h>
#include <stdint.h>

#define BATCH  8
#define SEQ    2048
#define MTOT   (BATCH*SEQ)      // 16384
#define DIN    64
#define HID    256
#define DMODEL 512
#define DINNER 1024
#define DSTATE 16
#define DTRANK 32
#define DCONV  4
#define DOUTD  64

// ---------------- scratch (allocation-free, __device__ globals) ----------------
__device__ float g_h    [MTOT*HID];
__device__ float g_u    [MTOT*DMODEL];
__device__ float g_xz   [MTOT*2*DINNER];   // (xm | z)
__device__ float g_xm   [MTOT*DINNER];
__device__ float g_dbl  [MTOT*64];         // [dt(32)|B(16)|C(16)]
__device__ float g_delta[MTOT*DINNER];
__device__ float g_y    [MTOT*DINNER];     // scan+gate out
__device__ float g_o1   [MTOT*DMODEL];
__device__ float g_h2   [MTOT*HID];

enum Act { ACT_NONE = 0, ACT_RELU = 1, ACT_SOFTPLUS = 2 };

// ---------------- helpers ----------------
__device__ __forceinline__ uint32_t pack_bf2(float a, float b) {
    __nv_bfloat162 h = __floats2bfloat162_rn(a, b);   // x=a (low), y=b (high)
    return *(uint32_t*)&h;
}

// mma.sync m16n8k16 bf16 -> fp32
__device__ __forceinline__ void mma16(float c[4], const uint32_t a[4], const uint32_t b[2]) {
    asm volatile(
        "mma.sync.aligned.m16n8k16.row.col.f32.bf16.bf16.f32 "
        "{%0,%1,%2,%3}, {%4,%5,%6,%7}, {%8,%9}, {%0,%1,%2,%3};\n"
        : "+f"(c[0]), "+f"(c[1]), "+f"(c[2]), "+f"(c[3])
        : "r"(a[0]), "r"(a[1]), "r"(a[2]), "r"(a[3]),
          "r"(b[0]), "r"(b[1]));
}

__device__ __forceinline__ void ldsm4(uint32_t* r, uint32_t saddr) {
    asm volatile("ldmatrix.sync.aligned.m8n8.x4.shared.b16 {%0,%1,%2,%3}, [%4];"
                 : "=r"(r[0]), "=r"(r[1]), "=r"(r[2]), "=r"(r[3]) : "r"(saddr));
}

// ---------------- bf16x3-split tensor-core GEMM (ldmatrix fragments) ----------------
// C[M,N] = act(A[M,K(lda)] * W[N,K]^T + bias), fp32 in/out.
// C = Ah Wh^T + Ah Wl^T + Al Wh^T  (Al*Wl dropped, ~2^-16 of |A||W|).
template<int BM,int BN,int WARPS_M,int WARPS_N,int ACT>
__global__ void __launch_bounds__(WARPS_M*WARPS_N*32)
gemm_bf(const float* __restrict__ A, const float* __restrict__ W,
        const float* __restrict__ bias, float* __restrict__ C,
        int M, int N, int K, int lda)
{
    constexpr int BK = 32, SK2 = BK + 8;      // halfword stride (40)
    constexpr int THREADS = WARPS_M*WARPS_N*32;
    constexpr int WM = BM/WARPS_M, WN = BN/WARPS_N;
    constexpr int MM = WM/16, MN = WN/8;
    static_assert(MN % 2 == 0, "MN must be even for paired B ldmatrix");

    __shared__ __align__(16) unsigned short sAh[BM*SK2];
    __shared__ __align__(16) unsigned short sAl[BM*SK2];
    __shared__ __align__(16) unsigned short sBh[BN*SK2];
    __shared__ __align__(16) unsigned short sBl[BN*SK2];

    const int tid  = threadIdx.x;
    const int lane = tid & 31;
    const int warp = tid >> 5;
    const int g    = lane >> 2;
    const int c4   = lane & 3;
    const int wrow = (warp / WARPS_N) * WM;
    const int wcol = (warp % WARPS_N) * WN;
    const int bm   = blockIdx.y * BM;
    const int bn   = blockIdx.x * BN;

    // per-lane ldmatrix row/col components
    const int a_m  = lane & 15;                 // A: matrix row within 16
    const int a_kc = (lane & 16) >> 1;          // A: +8 halves for matrices 2,3
    const int b_nt = (lane >> 4) & 1;           // B: second n8 tile for matrices 2,3
    const int b_n  = lane & 7;                  // B: row within 8
    const int b_kc = lane & 8;                  // B: +8 halves for matrices 1,3

    float acc[MM][MN][4];
#pragma unroll
    for (int i = 0; i < MM; i++)
#pragma unroll
        for (int j = 0; j < MN; j++)
#pragma unroll
            for (int q = 0; q < 4; q++) acc[i][j][q] = 0.f;

    for (int k0 = 0; k0 < K; k0 += BK) {
        // ---- fill tiles: fp32 load, bf16 hi/lo, 8B stores ----
        for (int i = tid; i < BM*(BK/4); i += THREADS) {
            int m  = i / (BK/4);
            int kc = (i % (BK/4)) * 4;
            float4 v = *(const float4*)(A + (size_t)(bm + m)*lda + k0 + kc);
            float hx = __bfloat162float(__float2bfloat16(v.x));
            float hy = __bfloat162float(__float2bfloat16(v.y));
            float hz = __bfloat162float(__float2bfloat16(v.z));
            float hw = __bfloat162float(__float2bfloat16(v.w));
            *(uint2*)(sAh + m*SK2 + kc) = make_uint2(pack_bf2(v.x, v.y), pack_bf2(v.z, v.w));
            *(uint2*)(sAl + m*SK2 + kc) = make_uint2(pack_bf2(v.x - hx, v.y - hy),
                                                     pack_bf2(v.z - hz, v.w - hw));
        }
        for (int i = tid; i < BN*(BK/4); i += THREADS) {
            int n  = i / (BK/4);
            int kc = (i % (BK/4)) * 4;
            float4 v = *(const float4*)(W + (size_t)(bn + n)*K + k0 + kc);
            float hx = __bfloat162float(__float2bfloat16(v.x));
            float hy = __bfloat162float(__float2bfloat16(v.y));
            float hz = __bfloat162float(__float2bfloat16(v.z));
            float hw = __bfloat162float(__float2bfloat16(v.w));
            *(uint2*)(sBh + n*SK2 + kc) = make_uint2(pack_bf2(v.x, v.y), pack_bf2(v.z, v.w));
            *(uint2*)(sBl + n*SK2 + kc) = make_uint2(pack_bf2(v.x - hx, v.y - hy),
                                                     pack_bf2(v.z - hz, v.w - hw));
        }
        __syncthreads();

        // ---- compute: 2 x k16 steps per BK=32 ----
#pragma unroll
        for (int kk = 0; kk < BK; kk += 16) {
            uint32_t ah[MM][4], al[MM][4];
#pragma unroll
            for (int mi = 0; mi < MM; mi++) {
                uint32_t off = (uint32_t)(((wrow + mi*16 + a_m)*SK2 + kk + a_kc) * 2);
                ldsm4(ah[mi], (uint32_t)__cvta_generic_to_shared(sAh) + off);
                ldsm4(al[mi], (uint32_t)__cvta_generic_to_shared(sAl) + off);
            }
            uint32_t bh[MN][2], bl[MN][2];
#pragma unroll
            for (int ni = 0; ni < MN; ni += 2) {
                uint32_t off = (uint32_t)((((wcol + (ni + b_nt)*8 + b_n)*SK2) + kk + b_kc) * 2);
                uint32_t rh[4], rl[4];
                ldsm4(rh, (uint32_t)__cvta_generic_to_shared(sBh) + off);
                ldsm4(rl, (uint32_t)__cvta_generic_to_shared(sBl) + off);
                bh[ni][0] = rh[0];   bh[ni][1] = rh[1];
                bh[ni+1][0] = rh[2]; bh[ni+1][1] = rh[3];
                bl[ni][0] = rl[0];   bl[ni][1] = rl[1];
                bl[ni+1][0] = rl[2]; bl[ni+1][1] = rl[3];
            }
#pragma unroll
            for (int ni = 0; ni < MN; ni++)
#pragma unroll
                for (int mi = 0; mi < MM; mi++) {
                    mma16(acc[mi][ni], al[mi], bh[ni]);
                    mma16(acc[mi][ni], ah[mi], bl[ni]);
                    mma16(acc[mi][ni], ah[mi], bh[ni]);
                }
        }
        __syncthreads();
    }

    // ---- epilogue ----
#pragma unroll
    for (int mi = 0; mi < MM; mi++) {
        int r0 = bm + wrow + mi*16 + g;
#pragma unroll
        for (int ni = 0; ni < MN; ni++) {
            int col = bn + wcol + ni*8 + 2*c4;
            float b0 = 0.f, b1 = 0.f;
            if (bias) { b0 = bias[col]; b1 = bias[col + 1]; }
            float v0 = acc[mi][ni][0] + b0;
            float v1 = acc[mi][ni][1] + b1;
            float v2 = acc[mi][ni][2] + b0;
            float v3 = acc[mi][ni][3] + b1;
            if (ACT == ACT_RELU) {
                v0 = fmaxf(v0, 0.f); v1 = fmaxf(v1, 0.f);
                v2 = fmaxf(v2, 0.f); v3 = fmaxf(v3, 0.f);
            }
            if (ACT == ACT_SOFTPLUS) {
                v0 = (v0 > 20.f) ? v0 : log1pf(__expf(v0));
                v1 = (v1 > 20.f) ? v1 : log1pf(__expf(v1));
                v2 = (v2 > 20.f) ? v2 : log1pf(__expf(v2));
                v3 = (v3 > 20.f) ? v3 : log1pf(__expf(v3));
            }
            *(float2*)(C + (size_t)r0*N + col)       = make_float2(v0, v1);
            *(float2*)(C + (size_t)(r0 + 8)*N + col) = make_float2(v2, v3);
        }
    }
}

// ---------------- depthwise causal conv1d (k=4) + bias + SiLU ----------------
__global__ void conv_silu_kernel(const float* __restrict__ conv_w,
                                 const float* __restrict__ conv_b)
{
    int idx = blockIdx.x * blockDim.x + threadIdx.x;
    if (idx >= MTOT * DINNER) return;
    int d  = idx % DINNER;
    int bt = idx / DINNER;
    int t  = bt % SEQ;
    int b  = bt / SEQ;

    float acc = conv_b[d];
#pragma unroll
    for (int j = 0; j < DCONV; j++) {
        int tt = t - (DCONV - 1) + j;
        if (tt >= 0)
            acc = fmaf(conv_w[d*DCONV + j],
                       g_xz[(size_t)(b*SEQ + tt)*(2*DINNER) + d], acc);
    }
    float sv = acc / (1.f + __expf(-acc));
    g_xm[(size_t)bt*DINNER + d] = sv;
}

// ---------------- selective scan + fused gating ----------------
__global__ void scan_kernel(const float* __restrict__ A_log,
                            const float* __restrict__ D_param)
{
    int gid = blockIdx.x * blockDim.x + threadIdx.x;
    int grp = gid >> 4;          // (b,d)
    int s   = gid & 15;
    if (grp >= BATCH * DINNER) return;
    int b = grp / DINNER;
    int d = grp % DINNER;

    const float Av = -__expf(A_log[d*DSTATE + s]);
    const float Dv = D_param[d];
    const float* drow = g_delta + (size_t)b*SEQ*DINNER + d;
    const float* xrow = g_xm    + (size_t)b*SEQ*DINNER + d;
    const float* zrow = g_xz    + (size_t)b*SEQ*(2*DINNER) + DINNER + d;
    const float* dblb = g_dbl   + (size_t)b*SEQ*64;
    float*       yrow = g_y     + (size_t)b*SEQ*DINNER + d;

    float h = 0.f;
    for (int t = 0; t < SEQ; t++) {
        float dt = drow[(size_t)t*DINNER];
        float xt = xrow[(size_t)t*DINNER];
        float Bt = dblb[t*64 + DTRANK + s];
        float Ct = dblb[t*64 + DTRANK + DSTATE + s];
        float dA = __expf(dt * Av);
        h = fmaf(dA, h, dt * xt * Bt);
        float p = h * Ct;
        p += __shfl_xor_sync(0xffffffffu, p, 8, 16);
        p += __shfl_xor_sync(0xffffffffu, p, 4, 16);
        p += __shfl_xor_sync(0xffffffffu, p, 2, 16);
        p += __shfl_xor_sync(0xffffffffu, p, 1, 16);
        if (s == 0) {
            float z  = zrow[(size_t)t*2*DINNER];
            float yv = p + xt * Dv;
            yrow[(size_t)t*DINNER] = yv * (z / (1.f + __expf(-z)));
        }
    }
}

// ---------------- host launch ----------------
static float* sym_addr(const void* symbol)
{
    void* p = nullptr;
    cudaGetSymbolAddress(&p, symbol);
    return (float*)p;
}

extern "C" void kernel_launch(void* const* d_in, const int* in_sizes, int n_in,
                              void* d_out, int out_size)
{
    const float* x         = (const float*)d_in[0];
    const float* enc_w1    = (const float*)d_in[1];
    const float* enc_b1    = (const float*)d_in[2];
    const float* enc_w2    = (const float*)d_in[3];
    const float* enc_b2    = (const float*)d_in[4];
    const float* in_proj_w = (const float*)d_in[5];
    const float* conv_w    = (const float*)d_in[6];
    const float* conv_b    = (const float*)d_in[7];
    const float* x_proj_w  = (const float*)d_in[8];
    const float* dt_proj_w = (const float*)d_in[9];
    const float* dt_proj_b = (const float*)d_in[10];
    const float* A_log     = (const float*)d_in[11];
    const float* D_param   = (const float*)d_in[12];
    const float* out_proj_w= (const float*)d_in[13];
    const float* dec_w1    = (const float*)d_in[14];
    const float* dec_b1    = (const float*)d_in[15];
    const float* dec_w2    = (const float*)d_in[16];
    const float* dec_b2    = (const float*)d_in[17];
    float* out = (float*)d_out;

    float* ph    = sym_addr(g_h);
    float* pu    = sym_addr(g_u);
    float* pxz   = sym_addr(g_xz);
    float* pxm   = sym_addr(g_xm);
    float* pdbl  = sym_addr(g_dbl);
    float* pdel  = sym_addr(g_delta);
    float* py    = sym_addr(g_y);
    float* po1   = sym_addr(g_o1);
    float* ph2   = sym_addr(g_h2);

    // 1. enc1: relu(x @ enc_w1^T + b1)   [16384,256] K=64
    gemm_bf<128,128,2,4,ACT_RELU><<<dim3(HID/128, MTOT/128), 256>>>(
        x, enc_w1, enc_b1, ph, MTOT, HID, DIN, DIN);

    // 2. enc2: u = h @ enc_w2^T + b2     [16384,512] K=256
    gemm_bf<128,128,2,4,ACT_NONE><<<dim3(DMODEL/128, MTOT/128), 256>>>(
        ph, enc_w2, enc_b2, pu, MTOT, DMODEL, HID, HID);

    // 3. in_proj: xz = u @ in_proj_w^T   [16384,2048] K=512
    gemm_bf<128,128,2,4,ACT_NONE><<<dim3(2*DINNER/128, MTOT/128), 256>>>(
        pu, in_proj_w, nullptr, pxz, MTOT, 2*DINNER, DMODEL, DMODEL);

    // 4. conv + bias + silu -> g_xm
    conv_silu_kernel<<<(MTOT*DINNER)/256, 256>>>(conv_w, conv_b);

    // 5. x_proj: dbl = xm @ x_proj_w^T   [16384,64] K=1024
    gemm_bf<128,64,4,2,ACT_NONE><<<dim3(1, MTOT/128), 256>>>(
        pxm, x_proj_w, nullptr, pdbl, MTOT, 64, DINNER, DINNER);

    // 6. dt_proj + softplus: delta       [16384,1024] K=32, lda=64
    gemm_bf<128,128,2,4,ACT_SOFTPLUS><<<dim3(DINNER/128, MTOT/128), 256>>>(
        pdbl, dt_proj_w, dt_proj_b, pdel, MTOT, DINNER, DTRANK, 64);

    // 7. selective scan + fused gating -> g_y
    scan_kernel<<<(BATCH*DINNER*DSTATE)/256, 256>>>(A_log, D_param);

    // 8. out_proj: o1 = y @ out_proj_w^T [16384,512] K=1024
    gemm_bf<128,128,2,4,ACT_NONE><<<dim3(DMODEL/128, MTOT/128), 256>>>(
        py, out_proj_w, nullptr, po1, MTOT, DMODEL, DINNER, DINNER);

    // 9. dec1: relu                      [16384,256] K=512
    gemm_bf<128,128,2,4,ACT_RELU><<<dim3(HID/128, MTOT/128), 256>>>(
        po1, dec_w1, dec_b1, ph2, MTOT, HID, DMODEL, DMODEL);

    // 10. dec2 -> out                    [16384,64] K=256
    gemm_bf<128,64,4,2,ACT_NONE><<<dim3(1, MTOT/128), 256>>>(
        ph2, dec_w2, dec_b2, out, MTOT, DOUTD, HID, HID);
}

// round 10
// speedup vs baseline: 1.0567x; 1.0567x over previous
#include <cuda_runtime.h>
#include <cuda_bf16.h>
#include <cuda_fp16.h>
#include <math.h>
#include <stdint.h>

#define BATCH  8
#define SEQ    2048
#define MTOT   (BATCH*SEQ)      // 16384
#define DIN    64
#define HID    256
#define DMODEL 512
#define DINNER 1024
#define DSTATE 16
#define DTRANK 32
#define DCONV  4
#define DOUTD  64

// ---------------- scratch (allocation-free, __device__ globals) ----------------
__device__ float g_h    [MTOT*HID];
__device__ float g_u    [MTOT*DMODEL];
__device__ float g_xz   [MTOT*2*DINNER];   // (xm | z)
__device__ float g_xm   [MTOT*DINNER];
__device__ float g_dbl  [MTOT*64];         // [dt(32)|B(16)|C(16)]
__device__ float g_delta[MTOT*DINNER];
__device__ float g_y    [MTOT*DINNER];     // scan+gate out
__device__ float g_o1   [MTOT*DMODEL];
__device__ float g_h2   [MTOT*HID];

enum Act { ACT_NONE = 0, ACT_RELU = 1, ACT_SOFTPLUS = 2 };
enum Fmt { FMT_BF16_SPLIT = 0, FMT_FP16_PLAIN = 1 };

// ---------------- helpers ----------------
__device__ __forceinline__ uint32_t pack_bf2(float a, float b) {
    __nv_bfloat162 h = __floats2bfloat162_rn(a, b);
    return *(uint32_t*)&h;
}
__device__ __forceinline__ uint32_t pack_h2(float a, float b) {
    __half2 h = __floats2half2_rn(a, b);
    return *(uint32_t*)&h;
}

__device__ __forceinline__ void mma16_bf(float c[4], const uint32_t a[4], const uint32_t b[2]) {
    asm volatile(
        "mma.sync.aligned.m16n8k16.row.col.f32.bf16.bf16.f32 "
        "{%0,%1,%2,%3}, {%4,%5,%6,%7}, {%8,%9}, {%0,%1,%2,%3};\n"
        : "+f"(c[0]), "+f"(c[1]), "+f"(c[2]), "+f"(c[3])
        : "r"(a[0]), "r"(a[1]), "r"(a[2]), "r"(a[3]),
          "r"(b[0]), "r"(b[1]));
}
__device__ __forceinline__ void mma16_fp(float c[4], const uint32_t a[4], const uint32_t b[2]) {
    asm volatile(
        "mma.sync.aligned.m16n8k16.row.col.f32.f16.f16.f32 "
        "{%0,%1,%2,%3}, {%4,%5,%6,%7}, {%8,%9}, {%0,%1,%2,%3};\n"
        : "+f"(c[0]), "+f"(c[1]), "+f"(c[2]), "+f"(c[3])
        : "r"(a[0]), "r"(a[1]), "r"(a[2]), "r"(a[3]),
          "r"(b[0]), "r"(b[1]));
}

__device__ __forceinline__ void ldsm4(uint32_t* r, uint32_t saddr) {
    asm volatile("ldmatrix.sync.aligned.m8n8.x4.shared.b16 {%0,%1,%2,%3}, [%4];"
                 : "=r"(r[0]), "=r"(r[1]), "=r"(r[2]), "=r"(r[3]) : "r"(saddr));
}

// ---------------- tensor-core GEMM (ldmatrix fragments) ----------------
// C[M,N] = act(inv_s * (A*sa)[M,K(lda)] * (W*sw)[N,K]^T + bias), fp32 in/out.
// FMT_BF16_SPLIT: bf16 hi/lo, 3 MMAs (fp32-class, sa=sw=inv_s=1).
// FMT_FP16_PLAIN: fp16, 1 MMA, power-of-2 scaling keeps values in normal range.
template<int BM,int BN,int WARPS_M,int WARPS_N,int ACT,int FMT>
__global__ void __launch_bounds__(WARPS_M*WARPS_N*32)
gemm_tc(const float* __restrict__ A, const float* __restrict__ W,
        const float* __restrict__ bias, float* __restrict__ C,
        int M, int N, int K, int lda,
        float sa, float sw, float inv_s)
{
    constexpr int BK = 32, SK2 = BK + 8;      // halfword stride (40)
    constexpr int THREADS = WARPS_M*WARPS_N*32;
    constexpr int WM = BM/WARPS_M, WN = BN/WARPS_N;
    constexpr int MM = WM/16, MN = WN/8;
    constexpr bool SPLIT = (FMT == FMT_BF16_SPLIT);
    static_assert(MN % 2 == 0, "MN must be even for paired B ldmatrix");

    __shared__ __align__(16) unsigned short sAh[BM*SK2];
    __shared__ __align__(16) unsigned short sBh[BN*SK2];
    __shared__ __align__(16) unsigned short sAl[SPLIT ? BM*SK2 : 8];
    __shared__ __align__(16) unsigned short sBl[SPLIT ? BN*SK2 : 8];

    const int tid  = threadIdx.x;
    const int lane = tid & 31;
    const int warp = tid >> 5;
    const int g    = lane >> 2;
    const int c4   = lane & 3;
    const int wrow = (warp / WARPS_N) * WM;
    const int wcol = (warp % WARPS_N) * WN;
    const int bm   = blockIdx.y * BM;
    const int bn   = blockIdx.x * BN;

    // ldmatrix lane mapping
    const int a_m  = lane & 15;
    const int a_kc = (lane & 16) >> 1;
    const int b_nt = (lane >> 4) & 1;
    const int b_n  = lane & 7;
    const int b_kc = lane & 8;

    float acc[MM][MN][4];
#pragma unroll
    for (int i = 0; i < MM; i++)
#pragma unroll
        for (int j = 0; j < MN; j++)
#pragma unroll
            for (int q = 0; q < 4; q++) acc[i][j][q] = 0.f;

    for (int k0 = 0; k0 < K; k0 += BK) {
        // ---- fill tiles ----
        for (int i = tid; i < BM*(BK/4); i += THREADS) {
            int m  = i / (BK/4);
            int kc = (i % (BK/4)) * 4;
            float4 v = *(const float4*)(A + (size_t)(bm + m)*lda + k0 + kc);
            if (SPLIT) {
                float hx = __bfloat162float(__float2bfloat16(v.x));
                float hy = __bfloat162float(__float2bfloat16(v.y));
                float hz = __bfloat162float(__float2bfloat16(v.z));
                float hw = __bfloat162float(__float2bfloat16(v.w));
                *(uint2*)(sAh + m*SK2 + kc) = make_uint2(pack_bf2(v.x, v.y), pack_bf2(v.z, v.w));
                *(uint2*)(sAl + m*SK2 + kc) = make_uint2(pack_bf2(v.x - hx, v.y - hy),
                                                         pack_bf2(v.z - hz, v.w - hw));
            } else {
                *(uint2*)(sAh + m*SK2 + kc) =
                    make_uint2(pack_h2(v.x*sa, v.y*sa), pack_h2(v.z*sa, v.w*sa));
            }
        }
        for (int i = tid; i < BN*(BK/4); i += THREADS) {
            int n  = i / (BK/4);
            int kc = (i % (BK/4)) * 4;
            float4 v = *(const float4*)(W + (size_t)(bn + n)*K + k0 + kc);
            if (SPLIT) {
                float hx = __bfloat162float(__float2bfloat16(v.x));
                float hy = __bfloat162float(__float2bfloat16(v.y));
                float hz = __bfloat162float(__float2bfloat16(v.z));
                float hw = __bfloat162float(__float2bfloat16(v.w));
                *(uint2*)(sBh + n*SK2 + kc) = make_uint2(pack_bf2(v.x, v.y), pack_bf2(v.z, v.w));
                *(uint2*)(sBl + n*SK2 + kc) = make_uint2(pack_bf2(v.x - hx, v.y - hy),
                                                         pack_bf2(v.z - hz, v.w - hw));
            } else {
                *(uint2*)(sBh + n*SK2 + kc) =
                    make_uint2(pack_h2(v.x*sw, v.y*sw), pack_h2(v.z*sw, v.w*sw));
            }
        }
        __syncthreads();

        // ---- compute ----
#pragma unroll
        for (int kk = 0; kk < BK; kk += 16) {
            uint32_t ah[MM][4], al[MM][4];
#pragma unroll
            for (int mi = 0; mi < MM; mi++) {
                uint32_t off = (uint32_t)(((wrow + mi*16 + a_m)*SK2 + kk + a_kc) * 2);
                ldsm4(ah[mi], (uint32_t)__cvta_generic_to_shared(sAh) + off);
                if (SPLIT) ldsm4(al[mi], (uint32_t)__cvta_generic_to_shared(sAl) + off);
            }
            uint32_t bh[MN][2], bl[MN][2];
#pragma unroll
            for (int ni = 0; ni < MN; ni += 2) {
                uint32_t off = (uint32_t)((((wcol + (ni + b_nt)*8 + b_n)*SK2) + kk + b_kc) * 2);
                uint32_t rh[4];
                ldsm4(rh, (uint32_t)__cvta_generic_to_shared(sBh) + off);
                bh[ni][0] = rh[0];   bh[ni][1] = rh[1];
                bh[ni+1][0] = rh[2]; bh[ni+1][1] = rh[3];
                if (SPLIT) {
                    uint32_t rl[4];
                    ldsm4(rl, (uint32_t)__cvta_generic_to_shared(sBl) + off);
                    bl[ni][0] = rl[0];   bl[ni][1] = rl[1];
                    bl[ni+1][0] = rl[2]; bl[ni+1][1] = rl[3];
                }
            }
#pragma unroll
            for (int ni = 0; ni < MN; ni++)
#pragma unroll
                for (int mi = 0; mi < MM; mi++) {
                    if (SPLIT) {
                        mma16_bf(acc[mi][ni], al[mi], bh[ni]);
                        mma16_bf(acc[mi][ni], ah[mi], bl[ni]);
                        mma16_bf(acc[mi][ni], ah[mi], bh[ni]);
                    } else {
                        mma16_fp(acc[mi][ni], ah[mi], bh[ni]);
                    }
                }
        }
        __syncthreads();
    }

    // ---- epilogue ----
#pragma unroll
    for (int mi = 0; mi < MM; mi++) {
        int r0 = bm + wrow + mi*16 + g;
#pragma unroll
        for (int ni = 0; ni < MN; ni++) {
            int col = bn + wcol + ni*8 + 2*c4;
            float b0 = 0.f, b1 = 0.f;
            if (bias) { b0 = bias[col]; b1 = bias[col + 1]; }
            float v0 = acc[mi][ni][0]*inv_s + b0;
            float v1 = acc[mi][ni][1]*inv_s + b1;
            float v2 = acc[mi][ni][2]*inv_s + b0;
            float v3 = acc[mi][ni][3]*inv_s + b1;
            if (ACT == ACT_RELU) {
                v0 = fmaxf(v0, 0.f); v1 = fmaxf(v1, 0.f);
                v2 = fmaxf(v2, 0.f); v3 = fmaxf(v3, 0.f);
            }
            if (ACT == ACT_SOFTPLUS) {
                v0 = (v0 > 20.f) ? v0 : log1pf(__expf(v0));
                v1 = (v1 > 20.f) ? v1 : log1pf(__expf(v1));
                v2 = (v2 > 20.f) ? v2 : log1pf(__expf(v2));
                v3 = (v3 > 20.f) ? v3 : log1pf(__expf(v3));
            }
            *(float2*)(C + (size_t)r0*N + col)       = make_float2(v0, v1);
            *(float2*)(C + (size_t)(r0 + 8)*N + col) = make_float2(v2, v3);
        }
    }
}

// ---------------- depthwise causal conv1d (k=4) + bias + SiLU ----------------
__global__ void conv_silu_kernel(const float* __restrict__ conv_w,
                                 const float* __restrict__ conv_b)
{
    int idx = blockIdx.x * blockDim.x + threadIdx.x;
    if (idx >= MTOT * DINNER) return;
    int d  = idx % DINNER;
    int bt = idx / DINNER;
    int t  = bt % SEQ;
    int b  = bt / SEQ;

    float acc = conv_b[d];
#pragma unroll
    for (int j = 0; j < DCONV; j++) {
        int tt = t - (DCONV - 1) + j;
        if (tt >= 0)
            acc = fmaf(conv_w[d*DCONV + j],
                       g_xz[(size_t)(b*SEQ + tt)*(2*DINNER) + d], acc);
    }
    float sv = acc / (1.f + __expf(-acc));
    g_xm[(size_t)bt*DINNER + d] = sv;
}

// ---------------- selective scan + fused gating ----------------
__global__ void scan_kernel(const float* __restrict__ A_log,
                            const float* __restrict__ D_param)
{
    int gid = blockIdx.x * blockDim.x + threadIdx.x;
    int grp = gid >> 4;          // (b,d)
    int s   = gid & 15;
    if (grp >= BATCH * DINNER) return;
    int b = grp / DINNER;
    int d = grp % DINNER;

    const float Av = -__expf(A_log[d*DSTATE + s]);
    const float Dv = D_param[d];
    const float* drow = g_delta + (size_t)b*SEQ*DINNER + d;
    const float* xrow = g_xm    + (size_t)b*SEQ*DINNER + d;
    const float* zrow = g_xz    + (size_t)b*SEQ*(2*DINNER) + DINNER + d;
    const float* dblb = g_dbl   + (size_t)b*SEQ*64;
    float*       yrow = g_y     + (size_t)b*SEQ*DINNER + d;

    float h = 0.f;
    for (int t = 0; t < SEQ; t++) {
        float dt = drow[(size_t)t*DINNER];
        float xt = xrow[(size_t)t*DINNER];
        float Bt = dblb[t*64 + DTRANK + s];
        float Ct = dblb[t*64 + DTRANK + DSTATE + s];
        float dA = __expf(dt * Av);
        h = fmaf(dA, h, dt * xt * Bt);
        float p = h * Ct;
        p += __shfl_xor_sync(0xffffffffu, p, 8, 16);
        p += __shfl_xor_sync(0xffffffffu, p, 4, 16);
        p += __shfl_xor_sync(0xffffffffu, p, 2, 16);
        p += __shfl_xor_sync(0xffffffffu, p, 1, 16);
        if (s == 0) {
            float z  = zrow[(size_t)t*2*DINNER];
            float yv = p + xt * Dv;
            yrow[(size_t)t*DINNER] = yv * (z / (1.f + __expf(-z)));
        }
    }
}

// ---------------- host launch ----------------
static float* sym_addr(const void* symbol)
{
    void* p = nullptr;
    cudaGetSymbolAddress(&p, symbol);
    return (float*)p;
}

extern "C" void kernel_launch(void* const* d_in, const int* in_sizes, int n_in,
                              void* d_out, int out_size)
{
    const float* x         = (const float*)d_in[0];
    const float* enc_w1    = (const float*)d_in[1];
    const float* enc_b1    = (const float*)d_in[2];
    const float* enc_w2    = (const float*)d_in[3];
    const float* enc_b2    = (const float*)d_in[4];
    const float* in_proj_w = (const float*)d_in[5];
    const float* conv_w    = (const float*)d_in[6];
    const float* conv_b    = (const float*)d_in[7];
    const float* x_proj_w  = (const float*)d_in[8];
    const float* dt_proj_w = (const float*)d_in[9];
    const float* dt_proj_b = (const float*)d_in[10];
    const float* A_log     = (const float*)d_in[11];
    const float* D_param   = (const float*)d_in[12];
    const float* out_proj_w= (const float*)d_in[13];
    const float* dec_w1    = (const float*)d_in[14];
    const float* dec_b1    = (const float*)d_in[15];
    const float* dec_w2    = (const float*)d_in[16];
    const float* dec_b2    = (const float*)d_in[17];
    float* out = (float*)d_out;

    float* ph    = sym_addr(g_h);
    float* pu    = sym_addr(g_u);
    float* pxz   = sym_addr(g_xz);
    float* pxm   = sym_addr(g_xm);
    float* pdbl  = sym_addr(g_dbl);
    float* pdel  = sym_addr(g_delta);
    float* py    = sym_addr(g_y);
    float* po1   = sym_addr(g_o1);
    float* ph2   = sym_addr(g_h2);

    // 1. enc1: relu(x @ enc_w1^T + b1)   [16384,256] K=64   (bf16x3)
    gemm_tc<128,128,2,4,ACT_RELU,FMT_BF16_SPLIT><<<dim3(HID/128, MTOT/128), 256>>>(
        x, enc_w1, enc_b1, ph, MTOT, HID, DIN, DIN, 1.f, 1.f, 1.f);

    // 2. enc2: u = h @ enc_w2^T + b2     [16384,512] K=256  (bf16x3)
    gemm_tc<128,128,2,4,ACT_NONE,FMT_BF16_SPLIT><<<dim3(DMODEL/128, MTOT/128), 256>>>(
        ph, enc_w2, enc_b2, pu, MTOT, DMODEL, HID, HID, 1.f, 1.f, 1.f);

    // 3. in_proj: xz = u @ in_proj_w^T   [16384,2048] K=512 (fp16, A*1024, W*64)
    gemm_tc<128,128,2,4,ACT_NONE,FMT_FP16_PLAIN><<<dim3(2*DINNER/128, MTOT/128), 256>>>(
        pu, in_proj_w, nullptr, pxz, MTOT, 2*DINNER, DMODEL, DMODEL,
        1024.f, 64.f, 1.f/65536.f);

    // 4. conv + bias + silu -> g_xm
    conv_silu_kernel<<<(MTOT*DINNER)/256, 256>>>(conv_w, conv_b);

    // 5. x_proj: dbl = xm @ x_proj_w^T   [16384,64] K=1024  (bf16x3)
    gemm_tc<128,64,4,2,ACT_NONE,FMT_BF16_SPLIT><<<dim3(1, MTOT/128), 256>>>(
        pxm, x_proj_w, nullptr, pdbl, MTOT, 64, DINNER, DINNER, 1.f, 1.f, 1.f);

    // 6. dt_proj + softplus: delta       [16384,1024] K=32, lda=64 (bf16x3)
    gemm_tc<128,128,2,4,ACT_SOFTPLUS,FMT_BF16_SPLIT><<<dim3(DINNER/128, MTOT/128), 256>>>(
        pdbl, dt_proj_w, dt_proj_b, pdel, MTOT, DINNER, DTRANK, 64, 1.f, 1.f, 1.f);

    // 7. selective scan + fused gating -> g_y
    scan_kernel<<<(BATCH*DINNER*DSTATE)/256, 256>>>(A_log, D_param);

    // 8. out_proj: o1 = y @ out_proj_w^T [16384,512] K=1024 (fp16, A*4096, W*64)
    gemm_tc<128,128,2,4,ACT_NONE,FMT_FP16_PLAIN><<<dim3(DMODEL/128, MTOT/128), 256>>>(
        py, out_proj_w, nullptr, po1, MTOT, DMODEL, DINNER, DINNER,
        4096.f, 64.f, 1.f/262144.f);

    // 9. dec1: relu                      [16384,256] K=512  (bf16x3)
    gemm_tc<128,128,2,4,ACT_RELU,FMT_BF16_SPLIT><<<dim3(HID/128, MTOT/128), 256>>>(
        po1, dec_w1, dec_b1, ph2, MTOT, HID, DMODEL, DMODEL, 1.f, 1.f, 1.f);

    // 10. dec2 -> out                    [16384,64] K=256   (bf16x3)
    gemm_tc<128,64,4,2,ACT_NONE,FMT_BF16_SPLIT><<<dim3(1, MTOT/128), 256>>>(
        ph2, dec_w2, dec_b2, out, MTOT, DOUTD, HID, HID, 1.f, 1.f, 1.f);
}